// round 15
// baseline (speedup 1.0000x reference)
#include <cuda_runtime.h>
#include <math.h>

// Problem constants
#define T_STEPS 300
#define BATCH   64
#define NH      512
#define D_IN    10
#define D_OUT   2

#define OUTS_SZ (T_STEPS*BATCH*D_OUT)
#define RSZ     (T_STEPS*BATCH*NH)
#define BN      (BATCH*NH)
#define NBLK    128

typedef unsigned long long u64;

// Persistent device scratch (no allocation — __device__ globals)
__device__ float g_rA[2][3][NH][BATCH];     // rates, k-major, double-buffered
__device__ unsigned g_cnt = 0;              // barrier arrival counter
__device__ unsigned g_gen = 0;              // barrier generation

// ---- f32x2 packed math (sm_103a) -----------------------------------------
__device__ __forceinline__ u64 pk2(float x, float y) {
    u64 r; asm("mov.b64 %0,{%1,%2};" : "=l"(r) : "f"(x), "f"(y)); return r;
}
__device__ __forceinline__ float2 upk2(u64 v) {
    float2 r; asm("mov.b64 {%0,%1},%2;" : "=f"(r.x), "=f"(r.y) : "l"(v)); return r;
}
__device__ __forceinline__ void fma2(u64 &d, u64 a, u64 b) {
    asm("fma.rn.f32x2 %0,%1,%2,%0;" : "+l"(d) : "l"(a), "l"(b));
}
__device__ __forceinline__ u64 add2(u64 a, u64 b) {
    u64 d; asm("add.rn.f32x2 %0,%1,%2;" : "=l"(d) : "l"(a), "l"(b)); return d;
}

// ---- scoped-atomic helpers for the grid barrier ---------------------------
__device__ __forceinline__ unsigned ld_acq(unsigned* p) {
    unsigned v;
    asm volatile("ld.acquire.gpu.u32 %0,[%1];" : "=r"(v) : "l"(p) : "memory");
    return v;
}
__device__ __forceinline__ void st_rel(unsigned* p, unsigned v) {
    asm volatile("st.release.gpu.u32 [%0],%1;" :: "l"(p), "r"(v) : "memory");
}
__device__ __forceinline__ unsigned atom_add_rel(unsigned* p, unsigned v) {
    unsigned old;
    asm volatile("atom.add.release.gpu.global.u32 %0,[%1],%2;"
                 : "=r"(old) : "l"(p), "r"(v) : "memory");
    return old;
}

// ---- dynamic shared memory layout -----------------------------------------
struct Smem {
    float Ws[3*NH][8];            // resident weights: 48 KB (proven layout)
    float RedA[8][64][9];         // K-reduction bank A: 18 KB (scalar access)
    float RedB[8][64][9];         // K-reduction bank B: 18 KB
    float stim_s[BATCH][D_IN];    // current stimulus: 2.5 KB
    float Win[D_IN][8];           // W_in_s1 columns: 320 B
};

// ---- grid barrier: release-arrival, NO full threadfence -------------------
// __syncthreads (cta-scope HB) -> thread-0 release-atomic arrival; HB is
// transitive through scopes, so an acquirer of g_gen sees ALL block stores.
// Avoids the MEMBAR drain stall (ordering rides in-flight). Same pattern as
// cooperative_groups grid.sync.
__device__ __forceinline__ void grid_bar(unsigned* mygen) {
    __syncthreads();
    if (threadIdx.x == 0) {
        unsigned g = *mygen;
        unsigned old = atom_add_rel(&g_cnt, 1);
        if (old == NBLK-1) { g_cnt = 0; st_rel(&g_gen, g + 1); }
        else { while (ld_acq(&g_gen) == g) { } }
    }
    __syncthreads();
    (*mygen)++;
}

// ---- panel primitives (R7 exact: proven fastest codegen) -------------------
// Thread (kh=tid>>4, rg=tid&15): 4 k-values x 4 batch x 8 cols per panel.
__device__ __forceinline__ void panel_ld(
    const float* const* __restrict__ S, int p, int kh, int rg, float4* dst)
{
    const float* A = S[p>>3];
    int k0 = (p&7) << 6;
    #pragma unroll
    for (int i = 0; i < 4; i++)
        dst[i] = __ldcg((const float4*)&A[(k0 + kh*4 + i)*BATCH + rg*4]);
}

__device__ __forceinline__ void panel_fma(
    const float4* __restrict__ cur, const float (* __restrict__ Ws)[8],
    int wrow, int kh, u64 acc[4][4])
{
    #pragma unroll
    for (int i = 0; i < 4; i++) {
        int wr = wrow + kh*4 + i;
        ulonglong2 wA = *(const ulonglong2*)&Ws[wr][0];   // full-warp broadcast
        ulonglong2 wB = *(const ulonglong2*)&Ws[wr][4];
        float4 av = cur[i];
        u64 a0 = pk2(av.x, av.x);
        u64 a1 = pk2(av.y, av.y);
        u64 a2 = pk2(av.z, av.z);
        u64 a3 = pk2(av.w, av.w);
        fma2(acc[0][0],a0,wA.x); fma2(acc[0][1],a0,wA.y);
        fma2(acc[0][2],a0,wB.x); fma2(acc[0][3],a0,wB.y);
        fma2(acc[1][0],a1,wA.x); fma2(acc[1][1],a1,wA.y);
        fma2(acc[1][2],a1,wB.x); fma2(acc[1][3],a1,wB.y);
        fma2(acc[2][0],a2,wA.x); fma2(acc[2][1],a2,wA.y);
        fma2(acc[2][2],a2,wB.x); fma2(acc[2][3],a2,wB.y);
        fma2(acc[3][0],a3,wA.x); fma2(acc[3][1],a3,wA.y);
        fma2(acc[3][2],a3,wB.x); fma2(acc[3][3],a3,wB.y);
    }
}

// One software-pipeline step over buffers bA..bD (step 4, depth-3 prefetch).
#define PIPE4(ACC) \
    { if (p + 3 < NPTOT) panel_ld(S, p + 3, kh, rg, bD); \
      panel_fma(bA, Ws, (p)*64, kh, ACC); \
      if (p + 4 < NPTOT) panel_ld(S, p + 4, kh, rg, bA); \
      panel_fma(bB, Ws, (p+1)*64, kh, ACC); \
      if (p + 5 < NPTOT) panel_ld(S, p + 5, kh, rg, bB); \
      panel_fma(bC, Ws, (p+2)*64, kh, ACC); \
      if (p + 6 < NPTOT) panel_ld(S, p + 6, kh, rg, bC); \
      panel_fma(bD, Ws, (p+3)*64, kh, ACC); }

// ---- single-acc accumulate (pmd blocks): 24 panels -> accA ----------------
__device__ __forceinline__ void compute_accum24(
    const float* const* __restrict__ S, const float (* __restrict__ Ws)[8],
    int kh, int rg, u64 accA[4][4])
{
    constexpr int NPTOT = 24;
    #pragma unroll
    for (int r = 0; r < 4; r++)
        #pragma unroll
        for (int c = 0; c < 4; c++) accA[r][c] = 0ull;

    float4 bA[4], bB[4], bC[4], bD[4];
    panel_ld(S, 0, kh, rg, bA);
    panel_ld(S, 1, kh, rg, bB);
    panel_ld(S, 2, kh, rg, bC);
    for (int p = 0; p < NPTOT; p += 4) PIPE4(accA)
}

// ---- dual-acc accumulate (m1s1 blocks): one 24-panel pipeline -------------
__device__ __forceinline__ void compute_accum16_8(
    const float* const* __restrict__ S, const float (* __restrict__ Ws)[8],
    int kh, int rg, u64 accA[4][4], u64 accB[4][4])
{
    constexpr int NPTOT = 24;
    #pragma unroll
    for (int r = 0; r < 4; r++)
        #pragma unroll
        for (int c = 0; c < 4; c++) { accA[r][c] = 0ull; accB[r][c] = 0ull; }

    float4 bA[4], bB[4], bC[4], bD[4];
    panel_ld(S, 0, kh, rg, bA);
    panel_ld(S, 1, kh, rg, bB);
    panel_ld(S, 2, kh, rg, bC);
    for (int p = 0;  p < 16;    p += 4) PIPE4(accA)
    for (int p = 16; p < NPTOT; p += 4) PIPE4(accB)
}

// ---- shfl-fold 16 k-slices -> 8, park partials in a Red bank --------------
__device__ __forceinline__ void reduce_to_red(
    u64 acc[4][4], float (* __restrict__ Red)[64][9], int tid)
{
    const int w = tid >> 5, rg = tid & 15;
    #pragma unroll
    for (int r = 0; r < 4; r++)
        #pragma unroll
        for (int c = 0; c < 4; c++)
            acc[r][c] = add2(acc[r][c], __shfl_xor_sync(0xffffffffu, acc[r][c], 16));
    if ((tid & 16) == 0) {
        #pragma unroll
        for (int r = 0; r < 4; r++)
            #pragma unroll
            for (int c = 0; c < 4; c++) {
                float2 v = upk2(acc[r][c]);
                // scalar stores (9-float rows would misalign float2)
                Red[w][rg*4 + r][2*c]   = v.x;
                Red[w][rg*4 + r][2*c+1] = v.y;
            }
    }
}

// ---- final: sum 8 partials, leaky update, tanh, COALESCED g_rA store ------
// Output remap: warp w owns col j=w, lane l owns batch rows 2l,2l+1 -> each
// warp writes ONE contiguous 256B g_rA row as aligned STG.64 (vs 32-way
// scatter). Red reads are <=2-way-conflict scalar LDS. d_out values stay
// register-deferred (rr0/rr1, flushed next step off the critical path).
__device__ __forceinline__ void finish_region(
    int reg, const float (* __restrict__ Red)[64][9], float biasv,
    bool add_stim, Smem& sm, int pw, int jj, int j, int b0,
    float& x0, float& x1, float& rr0, float& rr1)
{
    float2 out;
    #pragma unroll
    for (int h = 0; h < 2; h++) {
        int b = b0 + h;
        float s = 0.f;
        #pragma unroll
        for (int q = 0; q < 8; q++) s += Red[q][b][j];
        float v = s + biasv;
        if (add_stim) {
            #pragma unroll
            for (int k = 0; k < D_IN; k++)
                v = fmaf(sm.stim_s[b][k], sm.Win[k][j], v);
        }
        float& x = h ? x1 : x0;
        x = 0.8f*x + 0.2f*v;
        float rr = tanhf(x);
        (h ? rr1 : rr0) = rr;
        (h ? out.y : out.x) = rr;
    }
    __stcg((float2*)&g_rA[pw][reg][jj][b0], out);   // aligned, coalesced
}

// ---------------------------------------------------------------------------
// Persistent RNN: weights in smem, X state in registers, release-atomic grid
// barrier (no fence stall); coalesced g_rA stores; d_out deferred; fused
// readout. blocks [0,64): pmd (24 panels). [64,128): m1+s1 fused pipeline.
// ---------------------------------------------------------------------------
__global__ void __launch_bounds__(256,1) rnn_persistent(
    const float* __restrict__ W_rec_m1, const float* __restrict__ W_rec_pmd,
    const float* __restrict__ W_rec_s1, const float* __restrict__ W_pmd_m1,
    const float* __restrict__ b_pmd_m1, const float* __restrict__ W_m1_pmd,
    const float* __restrict__ b_m1_pmd, const float* __restrict__ W_s1_pmd,
    const float* __restrict__ b_s1_pmd, const float* __restrict__ W_in_s1,
    const float* __restrict__ b_in_s1, const float* __restrict__ W_out,
    const float* __restrict__ b_out,   const float* __restrict__ W_fb,
    const float* __restrict__ b_fb,    const float* __restrict__ stim,
    float* __restrict__ d_out)
{
    extern __shared__ char sraw[];
    Smem& sm = *reinterpret_cast<Smem*>(sraw);

    const int tid = threadIdx.x, bid = blockIdx.x;
    const bool pmdB = bid < 64;
    const int jb = (pmdB ? bid : bid - 64) << 3;
    // Epilogue ownership: warp = column, lane = batch pair (coalesced stores)
    const int jE  = tid >> 5;              // 0..7: column within group
    const int jjE = jb + jE;
    const int b0  = (tid & 31) << 1;       // batch rows b0, b0+1

    // ---- load weights into smem (once) ----
    if (pmdB) {
        for (int r = tid; r < NH; r += 256) {
            float wo0 = W_out[r*2], wo1 = W_out[r*2+1];
            #pragma unroll
            for (int q = 0; q < 8; q++) {
                int col = jb + q;
                sm.Ws[r][q]        = W_rec_pmd[r*NH + col];
                sm.Ws[NH + r][q]   = W_m1_pmd[r*NH + col]
                                   + wo0*W_fb[col] + wo1*W_fb[NH + col];
                sm.Ws[2*NH + r][q] = W_s1_pmd[r*NH + col];
            }
        }
    } else {
        for (int r = tid; r < NH; r += 256) {
            #pragma unroll
            for (int q = 0; q < 8; q++) {
                int col = jb + q;
                sm.Ws[r][q]        = W_rec_m1[r*NH + col];
                sm.Ws[NH + r][q]   = W_pmd_m1[r*NH + col];
                sm.Ws[2*NH + r][q] = W_rec_s1[r*NH + col];
            }
        }
        for (int i = tid; i < D_IN*8; i += 256)
            sm.Win[i>>3][i&7] = W_in_s1[(i>>3)*NH + jb + (i&7)];
    }

    // ---- fold biases into registers (epilogue mapping) ----
    float bias0, bias_ex = 0.f, bias_s1 = 0.f;
    if (pmdB) {
        bias0   = b_m1_pmd[jjE] + b_s1_pmd[jjE] + b_fb[jjE];
        bias_ex = b_out[0]*W_fb[jjE] + b_out[1]*W_fb[NH + jjE];
    } else {
        bias0   = b_pmd_m1[jjE];
        bias_s1 = b_in_s1[jjE];
    }

    // ---- zero parity-0 rates and t=0 rate slices ----
    {
        float* rA0 = &g_rA[0][0][0][0];
        for (int i = bid*256 + tid; i < 3*NH*BATCH; i += NBLK*256)
            __stcg(&rA0[i], 0.f);
        float* r0 = d_out + OUTS_SZ;
        for (int i = bid*256 + tid; i < BN; i += NBLK*256) {
            r0[i] = 0.f; r0[RSZ + i] = 0.f; r0[2*RSZ + i] = 0.f;
        }
    }

    float x_a0 = 0.f, x_a1 = 0.f;   // pmd (pmd-block) / m1 (m1s1-block)
    float x_b0 = 0.f, x_b1 = 0.f;   // s1 (m1s1-block)
    float r_a0 = 0.f, r_a1 = 0.f;   // deferred d_out rate values
    float r_b0 = 0.f, r_b1 = 0.f;

    unsigned mygen = ld_acq(&g_gen);
    grid_bar(&mygen);

    const int kh = tid >> 4, rg = tid & 15;
    u64 accA[4][4], accB[4][4];
    const float* S[3];

    for (int t = 1; t < T_STEPS; t++) {
        // ---- flush previous step's deferred d_out rate stores (off the
        //      critical path: fire-and-forget, overlaps the panel loads) ----
        if (t > 1) {
            float* rp = d_out + OUTS_SZ + (size_t)(t-1)*BN + b0*NH + jjE;
            if (pmdB) {                       // reg 1 (pmd)
                rp[RSZ] = r_a0; rp[RSZ + NH] = r_a1;
            } else {                          // reg 0 (m1), reg 2 (s1)
                rp[0] = r_a0;       rp[NH] = r_a1;
                rp[2*RSZ] = r_b0;   rp[2*RSZ + NH] = r_b1;
            }
        }

        const int pr = (t-1) & 1, pw = t & 1;
        const float* Am1  = &g_rA[pr][0][0][0];
        const float* Apmd = &g_rA[pr][1][0][0];
        const float* As1  = &g_rA[pr][2][0][0];

        if (pmdB) {
            S[0] = Apmd; S[1] = Am1; S[2] = As1;
            compute_accum24(S, sm.Ws, kh, rg, accA);
            reduce_to_red(accA, sm.RedA, tid);
            __syncthreads();
            float bv = (t == 1) ? bias0 : (bias0 + bias_ex);
            finish_region(1, sm.RedA, bv, false, sm, pw, jjE, jE, b0,
                          x_a0, x_a1, r_a0, r_a1);
        } else {
            // stage current stimulus (used after the Red sync)
            if (tid < 160)
                ((float4*)&sm.stim_s[0][0])[tid] =
                    __ldg((const float4*)(stim + (size_t)t*BATCH*D_IN) + tid);
            S[0] = Am1; S[1] = Apmd; S[2] = As1;
            compute_accum16_8(S, sm.Ws, kh, rg, accA, accB);
            reduce_to_red(accA, sm.RedA, tid);
            reduce_to_red(accB, sm.RedB, tid);
            __syncthreads();
            finish_region(0, sm.RedA, bias0,  false, sm, pw, jjE, jE, b0,
                          x_a0, x_a1, r_a0, r_a1);
            finish_region(2, sm.RedB, bias_s1, true, sm, pw, jjE, jE, b0,
                          x_b0, x_b1, r_b0, r_b1);
        }
        grid_bar(&mygen);   // release-arrival; syncthreads protects Red reuse
    }

    // ---- flush final step's deferred stores, then make them visible -------
    {
        float* rp = d_out + OUTS_SZ + (size_t)(T_STEPS-1)*BN + b0*NH + jjE;
        if (pmdB) {
            rp[RSZ] = r_a0; rp[RSZ + NH] = r_a1;
        } else {
            rp[0] = r_a0;       rp[NH] = r_a1;
            rp[2*RSZ] = r_b0;   rp[2*RSZ + NH] = r_b1;
        }
    }
    grid_bar(&mygen);

    // ---- fused readout: outs[t] = r_m1[t] @ W_out + b_out (t>=1) ----------
    for (int o = bid*256 + tid; o < OUTS_SZ; o += NBLK*256) {
        int t = o >> 7;                  // 128 outputs per timestep
        int rr = o & 127;
        int b = rr >> 1, d = rr & 1;
        if (t == 0) { d_out[o] = 0.f; continue; }
        const float* rm = d_out + OUTS_SZ + (size_t)t*BN + b*NH;
        float a0=0.f, a1=0.f, a2=0.f, a3=0.f;
        for (int k = 0; k < NH; k += 4) {
            float4 r4 = __ldcg((const float4*)&rm[k]);
            a0 = fmaf(r4.x, W_out[(k+0)*2 + d], a0);
            a1 = fmaf(r4.y, W_out[(k+1)*2 + d], a1);
            a2 = fmaf(r4.z, W_out[(k+2)*2 + d], a2);
            a3 = fmaf(r4.w, W_out[(k+3)*2 + d], a3);
        }
        d_out[o] = b_out[d] + (a0 + a1) + (a2 + a3);
    }
}

// ---------------------------------------------------------------------------
extern "C" void kernel_launch(void* const* d_in, const int* in_sizes, int n_in,
                              void* d_out, int out_size)
{
    const float* stim      = (const float*)d_in[0];
    const float* W_rec_m1  = (const float*)d_in[1];
    const float* W_rec_pmd = (const float*)d_in[2];
    const float* W_rec_s1  = (const float*)d_in[3];
    const float* W_pmd_m1  = (const float*)d_in[4];
    const float* b_pmd_m1  = (const float*)d_in[5];
    const float* W_m1_pmd  = (const float*)d_in[6];
    const float* b_m1_pmd  = (const float*)d_in[7];
    const float* W_s1_pmd  = (const float*)d_in[8];
    const float* b_s1_pmd  = (const float*)d_in[9];
    const float* W_in_s1   = (const float*)d_in[10];
    const float* b_in_s1   = (const float*)d_in[11];
    const float* W_out_m1  = (const float*)d_in[12];
    const float* b_out_m1  = (const float*)d_in[13];
    const float* W_fb_pmd  = (const float*)d_in[14];
    const float* b_fb_pmd  = (const float*)d_in[15];
    float* out = (float*)d_out;

    // Idempotent, capture-safe; no static guard.
    cudaFuncSetAttribute(rnn_persistent,
                         cudaFuncAttributeMaxDynamicSharedMemorySize,
                         (int)sizeof(Smem));

    rnn_persistent<<<NBLK, 256, sizeof(Smem)>>>(
        W_rec_m1, W_rec_pmd, W_rec_s1, W_pmd_m1, b_pmd_m1, W_m1_pmd,
        b_m1_pmd, W_s1_pmd, b_s1_pmd, W_in_s1, b_in_s1,
        W_out_m1, b_out_m1, W_fb_pmd, b_fb_pmd, stim, out);
}

// round 16
// speedup vs baseline: 1.0541x; 1.0541x over previous
#include <cuda_runtime.h>
#include <math.h>

// Problem constants
#define T_STEPS 300
#define BATCH   64
#define NH      512
#define D_IN    10
#define D_OUT   2

#define OUTS_SZ (T_STEPS*BATCH*D_OUT)
#define RSZ     (T_STEPS*BATCH*NH)
#define BN      (BATCH*NH)
#define NBLK    128

typedef unsigned long long u64;

// Persistent device scratch (no allocation — __device__ globals)
__device__ float g_rA[2][3][NH][BATCH];     // rates, k-major, double-buffered
__device__ unsigned g_cnt = 0;              // barrier arrival counter
__device__ unsigned g_gen = 0;              // barrier generation

// ---- f32x2 packed math (sm_103a) -----------------------------------------
__device__ __forceinline__ u64 pk2(float x, float y) {
    u64 r; asm("mov.b64 %0,{%1,%2};" : "=l"(r) : "f"(x), "f"(y)); return r;
}
__device__ __forceinline__ float2 upk2(u64 v) {
    float2 r; asm("mov.b64 {%0,%1},%2;" : "=f"(r.x), "=f"(r.y) : "l"(v)); return r;
}
__device__ __forceinline__ void fma2(u64 &d, u64 a, u64 b) {
    asm("fma.rn.f32x2 %0,%1,%2,%0;" : "+l"(d) : "l"(a), "l"(b));
}
__device__ __forceinline__ u64 add2(u64 a, u64 b) {
    u64 d; asm("add.rn.f32x2 %0,%1,%2;" : "=l"(d) : "l"(a), "l"(b)); return d;
}

// ---- scoped-atomic helpers for the grid barrier ---------------------------
__device__ __forceinline__ unsigned ld_acq(unsigned* p) {
    unsigned v;
    asm volatile("ld.acquire.gpu.u32 %0,[%1];" : "=r"(v) : "l"(p) : "memory");
    return v;
}
__device__ __forceinline__ void st_rel(unsigned* p, unsigned v) {
    asm volatile("st.release.gpu.u32 [%0],%1;" :: "l"(p), "r"(v) : "memory");
}
__device__ __forceinline__ unsigned atom_add_rel(unsigned* p, unsigned v) {
    unsigned old;
    asm volatile("atom.add.release.gpu.global.u32 %0,[%1],%2;"
                 : "=r"(old) : "l"(p), "r"(v) : "memory");
    return old;
}

// ---- dynamic shared memory layout -----------------------------------------
struct Smem {
    float Ws[3*NH][8];            // resident weights: 48 KB (proven layout)
    float RedA[8][64][9];         // K-reduction bank A: 18 KB (scalar access)
    float RedB[8][64][9];         // K-reduction bank B: 18 KB
    float OutT[2][8][72];         // rate transpose tiles (coalesced g_rA flush)
    float stim_s[BATCH][D_IN];    // current stimulus: 2.5 KB
    float Win[D_IN][8];           // W_in_s1 columns: 320 B
};

// ---- grid barrier: release-arrival (no MEMBAR drain stall) ----------------
// __syncthreads gives cta-scope HB; thread-0's atom.add.release.gpu arrival
// extends it to gpu scope transitively, so g_gen acquirers see ALL block
// stores. Ordering rides in-flight instead of stalling on a full fence.
// (R15 single-variable experiment vs R13's __threadfence barrier.)
__device__ __forceinline__ void grid_bar(unsigned* mygen) {
    __syncthreads();
    if (threadIdx.x == 0) {
        unsigned g = *mygen;
        unsigned old = atom_add_rel(&g_cnt, 1);
        if (old == NBLK-1) { g_cnt = 0; st_rel(&g_gen, g + 1); }
        else { while (ld_acq(&g_gen) == g) { } }
    }
    __syncthreads();
    (*mygen)++;
}

// ---- panel primitives (R7 exact: proven fastest codegen) -------------------
// Thread (kh=tid>>4, rg=tid&15): 4 k-values x 4 batch x 8 cols per panel.
__device__ __forceinline__ void panel_ld(
    const float* const* __restrict__ S, int p, int kh, int rg, float4* dst)
{
    const float* A = S[p>>3];
    int k0 = (p&7) << 6;
    #pragma unroll
    for (int i = 0; i < 4; i++)
        dst[i] = __ldcg((const float4*)&A[(k0 + kh*4 + i)*BATCH + rg*4]);
}

__device__ __forceinline__ void panel_fma(
    const float4* __restrict__ cur, const float (* __restrict__ Ws)[8],
    int wrow, int kh, u64 acc[4][4])
{
    #pragma unroll
    for (int i = 0; i < 4; i++) {
        int wr = wrow + kh*4 + i;
        ulonglong2 wA = *(const ulonglong2*)&Ws[wr][0];   // full-warp broadcast
        ulonglong2 wB = *(const ulonglong2*)&Ws[wr][4];
        float4 av = cur[i];
        u64 a0 = pk2(av.x, av.x);
        u64 a1 = pk2(av.y, av.y);
        u64 a2 = pk2(av.z, av.z);
        u64 a3 = pk2(av.w, av.w);
        fma2(acc[0][0],a0,wA.x); fma2(acc[0][1],a0,wA.y);
        fma2(acc[0][2],a0,wB.x); fma2(acc[0][3],a0,wB.y);
        fma2(acc[1][0],a1,wA.x); fma2(acc[1][1],a1,wA.y);
        fma2(acc[1][2],a1,wB.x); fma2(acc[1][3],a1,wB.y);
        fma2(acc[2][0],a2,wA.x); fma2(acc[2][1],a2,wA.y);
        fma2(acc[2][2],a2,wB.x); fma2(acc[2][3],a2,wB.y);
        fma2(acc[3][0],a3,wA.x); fma2(acc[3][1],a3,wA.y);
        fma2(acc[3][2],a3,wB.x); fma2(acc[3][3],a3,wB.y);
    }
}

// One software-pipeline step over buffers bA..bD (step 4, depth-3 prefetch).
#define PIPE4(ACC) \
    { if (p + 3 < NPTOT) panel_ld(S, p + 3, kh, rg, bD); \
      panel_fma(bA, Ws, (p)*64, kh, ACC); \
      if (p + 4 < NPTOT) panel_ld(S, p + 4, kh, rg, bA); \
      panel_fma(bB, Ws, (p+1)*64, kh, ACC); \
      if (p + 5 < NPTOT) panel_ld(S, p + 5, kh, rg, bB); \
      panel_fma(bC, Ws, (p+2)*64, kh, ACC); \
      if (p + 6 < NPTOT) panel_ld(S, p + 6, kh, rg, bC); \
      panel_fma(bD, Ws, (p+3)*64, kh, ACC); }

// ---- single-acc accumulate (pmd blocks): 24 panels -> accA ----------------
__device__ __forceinline__ void compute_accum24(
    const float* const* __restrict__ S, const float (* __restrict__ Ws)[8],
    int kh, int rg, u64 accA[4][4])
{
    constexpr int NPTOT = 24;
    #pragma unroll
    for (int r = 0; r < 4; r++)
        #pragma unroll
        for (int c = 0; c < 4; c++) accA[r][c] = 0ull;

    float4 bA[4], bB[4], bC[4], bD[4];
    panel_ld(S, 0, kh, rg, bA);
    panel_ld(S, 1, kh, rg, bB);
    panel_ld(S, 2, kh, rg, bC);
    for (int p = 0; p < NPTOT; p += 4) PIPE4(accA)
}

// ---- dual-acc accumulate (m1s1 blocks): one 24-panel pipeline -------------
__device__ __forceinline__ void compute_accum16_8(
    const float* const* __restrict__ S, const float (* __restrict__ Ws)[8],
    int kh, int rg, u64 accA[4][4], u64 accB[4][4])
{
    constexpr int NPTOT = 24;
    #pragma unroll
    for (int r = 0; r < 4; r++)
        #pragma unroll
        for (int c = 0; c < 4; c++) { accA[r][c] = 0ull; accB[r][c] = 0ull; }

    float4 bA[4], bB[4], bC[4], bD[4];
    panel_ld(S, 0, kh, rg, bA);
    panel_ld(S, 1, kh, rg, bB);
    panel_ld(S, 2, kh, rg, bC);
    for (int p = 0;  p < 16;    p += 4) PIPE4(accA)
    for (int p = 16; p < NPTOT; p += 4) PIPE4(accB)
}

// ---- shfl-fold 16 k-slices -> 8, park partials in a Red bank --------------
__device__ __forceinline__ void reduce_to_red(
    u64 acc[4][4], float (* __restrict__ Red)[64][9], int tid)
{
    const int w = tid >> 5, rg = tid & 15;
    #pragma unroll
    for (int r = 0; r < 4; r++)
        #pragma unroll
        for (int c = 0; c < 4; c++)
            acc[r][c] = add2(acc[r][c], __shfl_xor_sync(0xffffffffu, acc[r][c], 16));
    if ((tid & 16) == 0) {
        #pragma unroll
        for (int r = 0; r < 4; r++)
            #pragma unroll
            for (int c = 0; c < 4; c++) {
                float2 v = upk2(acc[r][c]);
                // scalar stores (9-float rows would misalign float2)
                Red[w][rg*4 + r][2*c]   = v.x;
                Red[w][rg*4 + r][2*c+1] = v.y;
            }
    }
}

// ---- final: sum 8 partials, leaky update, tanh -> OutT smem tile ----------
// d_out rate values stay register-deferred (rr0/rr1, flushed next step).
__device__ __forceinline__ void finish_region(
    const float (* __restrict__ Red)[64][9], float biasv,
    bool add_stim, Smem& sm, float (* __restrict__ OutT)[72],
    float& x0, float& x1, float& rr0, float& rr1)
{
    const int tid = threadIdx.x;
    const int j = tid & 7;
    #pragma unroll
    for (int h = 0; h < 2; h++) {
        int b = (tid >> 3) + h*32;
        float s = 0.f;
        #pragma unroll
        for (int q = 0; q < 8; q++) s += Red[q][b][j];
        float v = s + biasv;
        if (add_stim) {
            #pragma unroll
            for (int k = 0; k < D_IN; k++)
                v = fmaf(sm.stim_s[b][k], sm.Win[k][j], v);
        }
        float& x = h ? x1 : x0;
        x = 0.8f*x + 0.2f*v;
        float rr = tanhf(x);
        (h ? rr1 : rr0) = rr;
        OutT[j][b] = rr;              // smem transpose tile (~2-way conflicts)
    }
}

// ---- coalesced g_rA flush: OutT[8][72] -> one 8x64 k-major region ---------
// All 256 threads: thread (jjl=tid>>5, b2=tid&31) moves one float2; per warp
// the stores cover one contiguous 256B g_rA row (fully coalesced).
__device__ __forceinline__ void flush_rates(
    const float (* __restrict__ OutT)[72], int pw, int reg, int jb, int tid)
{
    int jjl = tid >> 5, b2 = tid & 31;
    float2 v = *(const float2*)&OutT[jjl][b2*2];
    __stcg((float2*)&g_rA[pw][reg][jb + jjl][b2*2], v);
}

// ---------------------------------------------------------------------------
// Persistent RNN: weights in smem, X state in registers, release-atomic grid
// barrier; g_rA writes smem-transposed+coalesced; d_out deferred; fused
// readout. blocks [0,64): pmd (24 panels). [64,128): m1+s1 fused pipeline.
// ---------------------------------------------------------------------------
__global__ void __launch_bounds__(256,1) rnn_persistent(
    const float* __restrict__ W_rec_m1, const float* __restrict__ W_rec_pmd,
    const float* __restrict__ W_rec_s1, const float* __restrict__ W_pmd_m1,
    const float* __restrict__ b_pmd_m1, const float* __restrict__ W_m1_pmd,
    const float* __restrict__ b_m1_pmd, const float* __restrict__ W_s1_pmd,
    const float* __restrict__ b_s1_pmd, const float* __restrict__ W_in_s1,
    const float* __restrict__ b_in_s1, const float* __restrict__ W_out,
    const float* __restrict__ b_out,   const float* __restrict__ W_fb,
    const float* __restrict__ b_fb,    const float* __restrict__ stim,
    float* __restrict__ d_out)
{
    extern __shared__ char sraw[];
    Smem& sm = *reinterpret_cast<Smem*>(sraw);

    const int tid = threadIdx.x, bid = blockIdx.x;
    const bool pmdB = bid < 64;
    const int jb = (pmdB ? bid : bid - 64) << 3;
    const int jj = jb + (tid & 7);
    const int b0 = tid >> 3;               // batch row for h=0 (h=1: +32)

    // ---- load weights into smem (once) ----
    if (pmdB) {
        for (int r = tid; r < NH; r += 256) {
            float wo0 = W_out[r*2], wo1 = W_out[r*2+1];
            #pragma unroll
            for (int q = 0; q < 8; q++) {
                int col = jb + q;
                sm.Ws[r][q]        = W_rec_pmd[r*NH + col];
                sm.Ws[NH + r][q]   = W_m1_pmd[r*NH + col]
                                   + wo0*W_fb[col] + wo1*W_fb[NH + col];
                sm.Ws[2*NH + r][q] = W_s1_pmd[r*NH + col];
            }
        }
    } else {
        for (int r = tid; r < NH; r += 256) {
            #pragma unroll
            for (int q = 0; q < 8; q++) {
                int col = jb + q;
                sm.Ws[r][q]        = W_rec_m1[r*NH + col];
                sm.Ws[NH + r][q]   = W_pmd_m1[r*NH + col];
                sm.Ws[2*NH + r][q] = W_rec_s1[r*NH + col];
            }
        }
        for (int i = tid; i < D_IN*8; i += 256)
            sm.Win[i>>3][i&7] = W_in_s1[(i>>3)*NH + jb + (i&7)];
    }

    // ---- fold biases into registers ----
    float bias0, bias_ex = 0.f, bias_s1 = 0.f;
    if (pmdB) {
        bias0   = b_m1_pmd[jj] + b_s1_pmd[jj] + b_fb[jj];
        bias_ex = b_out[0]*W_fb[jj] + b_out[1]*W_fb[NH + jj];
    } else {
        bias0   = b_pmd_m1[jj];
        bias_s1 = b_in_s1[jj];
    }

    // ---- zero parity-0 rates and t=0 rate slices ----
    {
        float* rA0 = &g_rA[0][0][0][0];
        for (int i = bid*256 + tid; i < 3*NH*BATCH; i += NBLK*256)
            __stcg(&rA0[i], 0.f);
        float* r0 = d_out + OUTS_SZ;
        for (int i = bid*256 + tid; i < BN; i += NBLK*256) {
            r0[i] = 0.f; r0[RSZ + i] = 0.f; r0[2*RSZ + i] = 0.f;
        }
    }

    float x_a0 = 0.f, x_a1 = 0.f;   // pmd (pmd-block) / m1 (m1s1-block)
    float x_b0 = 0.f, x_b1 = 0.f;   // s1 (m1s1-block)
    float r_a0 = 0.f, r_a1 = 0.f;   // deferred d_out rate values
    float r_b0 = 0.f, r_b1 = 0.f;

    unsigned mygen = ld_acq(&g_gen);
    grid_bar(&mygen);

    const int kh = tid >> 4, rg = tid & 15;
    u64 accA[4][4], accB[4][4];
    const float* S[3];

    for (int t = 1; t < T_STEPS; t++) {
        // ---- flush previous step's deferred d_out rate stores (off the
        //      critical path: fire-and-forget, overlaps the panel loads) ----
        if (t > 1) {
            float* rp = d_out + OUTS_SZ + (size_t)(t-1)*BN + b0*NH + jj;
            if (pmdB) {                       // reg 1 (pmd)
                rp[RSZ] = r_a0; rp[RSZ + 32*NH] = r_a1;
            } else {                          // reg 0 (m1), reg 2 (s1)
                rp[0] = r_a0;       rp[32*NH] = r_a1;
                rp[2*RSZ] = r_b0;   rp[2*RSZ + 32*NH] = r_b1;
            }
        }

        const int pr = (t-1) & 1, pw = t & 1;
        const float* Am1  = &g_rA[pr][0][0][0];
        const float* Apmd = &g_rA[pr][1][0][0];
        const float* As1  = &g_rA[pr][2][0][0];

        if (pmdB) {
            S[0] = Apmd; S[1] = Am1; S[2] = As1;
            compute_accum24(S, sm.Ws, kh, rg, accA);
            reduce_to_red(accA, sm.RedA, tid);
            __syncthreads();
            float bv = (t == 1) ? bias0 : (bias0 + bias_ex);
            finish_region(sm.RedA, bv, false, sm, sm.OutT[0],
                          x_a0, x_a1, r_a0, r_a1);
            __syncthreads();
            flush_rates(sm.OutT[0], pw, 1, jb, tid);
        } else {
            // stage current stimulus (used after the Red sync)
            if (tid < 160)
                ((float4*)&sm.stim_s[0][0])[tid] =
                    __ldg((const float4*)(stim + (size_t)t*BATCH*D_IN) + tid);
            S[0] = Am1; S[1] = Apmd; S[2] = As1;
            compute_accum16_8(S, sm.Ws, kh, rg, accA, accB);
            reduce_to_red(accA, sm.RedA, tid);
            reduce_to_red(accB, sm.RedB, tid);
            __syncthreads();
            finish_region(sm.RedA, bias0,  false, sm, sm.OutT[0],
                          x_a0, x_a1, r_a0, r_a1);
            finish_region(sm.RedB, bias_s1, true, sm, sm.OutT[1],
                          x_b0, x_b1, r_b0, r_b1);
            __syncthreads();
            flush_rates(sm.OutT[0], pw, 0, jb, tid);
            flush_rates(sm.OutT[1], pw, 2, jb, tid);
        }
        grid_bar(&mygen);   // release-arrival; syncthreads protects Red/OutT
    }

    // ---- flush final step's deferred stores, then make them visible -------
    {
        float* rp = d_out + OUTS_SZ + (size_t)(T_STEPS-1)*BN + b0*NH + jj;
        if (pmdB) {
            rp[RSZ] = r_a0; rp[RSZ + 32*NH] = r_a1;
        } else {
            rp[0] = r_a0;       rp[32*NH] = r_a1;
            rp[2*RSZ] = r_b0;   rp[2*RSZ + 32*NH] = r_b1;
        }
    }
    grid_bar(&mygen);

    // ---- fused readout: outs[t] = r_m1[t] @ W_out + b_out (t>=1) ----------
    for (int o = bid*256 + tid; o < OUTS_SZ; o += NBLK*256) {
        int t = o >> 7;                  // 128 outputs per timestep
        int rr = o & 127;
        int b = rr >> 1, d = rr & 1;
        if (t == 0) { d_out[o] = 0.f; continue; }
        const float* rm = d_out + OUTS_SZ + (size_t)t*BN + b*NH;
        float a0=0.f, a1=0.f, a2=0.f, a3=0.f;
        for (int k = 0; k < NH; k += 4) {
            float4 r4 = __ldcg((const float4*)&rm[k]);
            a0 = fmaf(r4.x, W_out[(k+0)*2 + d], a0);
            a1 = fmaf(r4.y, W_out[(k+1)*2 + d], a1);
            a2 = fmaf(r4.z, W_out[(k+2)*2 + d], a2);
            a3 = fmaf(r4.w, W_out[(k+3)*2 + d], a3);
        }
        d_out[o] = b_out[d] + (a0 + a1) + (a2 + a3);
    }
}

// ---------------------------------------------------------------------------
extern "C" void kernel_launch(void* const* d_in, const int* in_sizes, int n_in,
                              void* d_out, int out_size)
{
    const float* stim      = (const float*)d_in[0];
    const float* W_rec_m1  = (const float*)d_in[1];
    const float* W_rec_pmd = (const float*)d_in[2];
    const float* W_rec_s1  = (const float*)d_in[3];
    const float* W_pmd_m1  = (const float*)d_in[4];
    const float* b_pmd_m1  = (const float*)d_in[5];
    const float* W_m1_pmd  = (const float*)d_in[6];
    const float* b_m1_pmd  = (const float*)d_in[7];
    const float* W_s1_pmd  = (const float*)d_in[8];
    const float* b_s1_pmd  = (const float*)d_in[9];
    const float* W_in_s1   = (const float*)d_in[10];
    const float* b_in_s1   = (const float*)d_in[11];
    const float* W_out_m1  = (const float*)d_in[12];
    const float* b_out_m1  = (const float*)d_in[13];
    const float* W_fb_pmd  = (const float*)d_in[14];
    const float* b_fb_pmd  = (const float*)d_in[15];
    float* out = (float*)d_out;

    // Idempotent, capture-safe; no static guard.
    cudaFuncSetAttribute(rnn_persistent,
                         cudaFuncAttributeMaxDynamicSharedMemorySize,
                         (int)sizeof(Smem));

    rnn_persistent<<<NBLK, 256, sizeof(Smem)>>>(
        W_rec_m1, W_rec_pmd, W_rec_s1, W_pmd_m1, b_pmd_m1, W_m1_pmd,
        b_m1_pmd, W_s1_pmd, b_s1_pmd, W_in_s1, b_in_s1,
        W_out_m1, b_out_m1, W_fb_pmd, b_fb_pmd, stim, out);
}

// round 17
// speedup vs baseline: 1.0651x; 1.0104x over previous
#include <cuda_runtime.h>
#include <math.h>

// Problem constants
#define T_STEPS 300
#define BATCH   64
#define NH      512
#define D_IN    10
#define D_OUT   2

#define OUTS_SZ (T_STEPS*BATCH*D_OUT)
#define RSZ     (T_STEPS*BATCH*NH)
#define BN      (BATCH*NH)
#define NBLK    128

typedef unsigned long long u64;

// Persistent device scratch (no allocation — __device__ globals)
__device__ float g_rA[2][3][NH][BATCH];     // rates, k-major, double-buffered
__device__ unsigned g_cnt = 0;              // barrier arrival counter
__device__ unsigned g_gen = 0;              // barrier generation

// ---- f32x2 packed math (sm_103a) -----------------------------------------
__device__ __forceinline__ u64 pk2(float x, float y) {
    u64 r; asm("mov.b64 %0,{%1,%2};" : "=l"(r) : "f"(x), "f"(y)); return r;
}
__device__ __forceinline__ float2 upk2(u64 v) {
    float2 r; asm("mov.b64 {%0,%1},%2;" : "=f"(r.x), "=f"(r.y) : "l"(v)); return r;
}
__device__ __forceinline__ void fma2(u64 &d, u64 a, u64 b) {
    asm("fma.rn.f32x2 %0,%1,%2,%0;" : "+l"(d) : "l"(a), "l"(b));
}
__device__ __forceinline__ u64 add2(u64 a, u64 b) {
    u64 d; asm("add.rn.f32x2 %0,%1,%2;" : "=l"(d) : "l"(a), "l"(b)); return d;
}

// ---- scoped-atomic helpers for the grid barrier ---------------------------
__device__ __forceinline__ unsigned ld_acq(unsigned* p) {
    unsigned v;
    asm volatile("ld.acquire.gpu.u32 %0,[%1];" : "=r"(v) : "l"(p) : "memory");
    return v;
}
__device__ __forceinline__ void st_rel(unsigned* p, unsigned v) {
    asm volatile("st.release.gpu.u32 [%0],%1;" :: "l"(p), "r"(v) : "memory");
}
__device__ __forceinline__ unsigned atom_add_rel(unsigned* p, unsigned v) {
    unsigned old;
    asm volatile("atom.add.release.gpu.global.u32 %0,[%1],%2;"
                 : "=r"(old) : "l"(p), "r"(v) : "memory");
    return old;
}

// ---- dynamic shared memory layout -----------------------------------------
struct Smem {
    float Ws[3*NH][8];            // resident weights: 48 KB (proven layout)
    float RedA[8][64][9];         // K-reduction bank A: 18 KB (scalar access)
    float RedB[8][64][9];         // K-reduction bank B: 18 KB
    float OutT[2][8][72];         // rate transpose tiles (coalesced g_rA flush)
    float stim_s[BATCH][D_IN];    // current stimulus: 2.5 KB
    float Win[D_IN][8];           // W_in_s1 columns: 320 B
};

// ---- grid barrier: release-arrival (no MEMBAR drain stall) ----------------
// __syncthreads gives cta-scope HB; thread-0's atom.add.release.gpu arrival
// extends it to gpu scope transitively, so g_gen acquirers see ALL block
// stores. (R15-proven: ~24us faster than the __threadfence variant.)
__device__ __forceinline__ void grid_bar(unsigned* mygen) {
    __syncthreads();
    if (threadIdx.x == 0) {
        unsigned g = *mygen;
        unsigned old = atom_add_rel(&g_cnt, 1);
        if (old == NBLK-1) { g_cnt = 0; st_rel(&g_gen, g + 1); }
        else { while (ld_acq(&g_gen) == g) { } }
    }
    __syncthreads();
    (*mygen)++;
}

// ---- panel primitives (R7 exact: proven fastest codegen) -------------------
// Thread (kh=tid>>4, rg=tid&15): 4 k-values x 4 batch x 8 cols per panel.
__device__ __forceinline__ void panel_ld(
    const float* const* __restrict__ S, int p, int kh, int rg, float4* dst)
{
    const float* A = S[p>>3];
    int k0 = (p&7) << 6;
    #pragma unroll
    for (int i = 0; i < 4; i++)
        dst[i] = __ldcg((const float4*)&A[(k0 + kh*4 + i)*BATCH + rg*4]);
}

__device__ __forceinline__ void panel_fma(
    const float4* __restrict__ cur, const float (* __restrict__ Ws)[8],
    int wrow, int kh, u64 acc[4][4])
{
    #pragma unroll
    for (int i = 0; i < 4; i++) {
        int wr = wrow + kh*4 + i;
        ulonglong2 wA = *(const ulonglong2*)&Ws[wr][0];   // full-warp broadcast
        ulonglong2 wB = *(const ulonglong2*)&Ws[wr][4];
        float4 av = cur[i];
        u64 a0 = pk2(av.x, av.x);
        u64 a1 = pk2(av.y, av.y);
        u64 a2 = pk2(av.z, av.z);
        u64 a3 = pk2(av.w, av.w);
        fma2(acc[0][0],a0,wA.x); fma2(acc[0][1],a0,wA.y);
        fma2(acc[0][2],a0,wB.x); fma2(acc[0][3],a0,wB.y);
        fma2(acc[1][0],a1,wA.x); fma2(acc[1][1],a1,wA.y);
        fma2(acc[1][2],a1,wB.x); fma2(acc[1][3],a1,wB.y);
        fma2(acc[2][0],a2,wA.x); fma2(acc[2][1],a2,wA.y);
        fma2(acc[2][2],a2,wB.x); fma2(acc[2][3],a2,wB.y);
        fma2(acc[3][0],a3,wA.x); fma2(acc[3][1],a3,wA.y);
        fma2(acc[3][2],a3,wB.x); fma2(acc[3][3],a3,wB.y);
    }
}

// One software-pipeline step over buffers bA..bD (step 4, depth-3 prefetch).
#define PIPE4(ACC) \
    { if (p + 3 < NPTOT) panel_ld(S, p + 3, kh, rg, bD); \
      panel_fma(bA, Ws, (p)*64, kh, ACC); \
      if (p + 4 < NPTOT) panel_ld(S, p + 4, kh, rg, bA); \
      panel_fma(bB, Ws, (p+1)*64, kh, ACC); \
      if (p + 5 < NPTOT) panel_ld(S, p + 5, kh, rg, bB); \
      panel_fma(bC, Ws, (p+2)*64, kh, ACC); \
      if (p + 6 < NPTOT) panel_ld(S, p + 6, kh, rg, bC); \
      panel_fma(bD, Ws, (p+3)*64, kh, ACC); }

// ---- single-acc accumulate (pmd blocks): 24 panels -> accA ----------------
__device__ __forceinline__ void compute_accum24(
    const float* const* __restrict__ S, const float (* __restrict__ Ws)[8],
    int kh, int rg, u64 accA[4][4])
{
    constexpr int NPTOT = 24;
    #pragma unroll
    for (int r = 0; r < 4; r++)
        #pragma unroll
        for (int c = 0; c < 4; c++) accA[r][c] = 0ull;

    float4 bA[4], bB[4], bC[4], bD[4];
    panel_ld(S, 0, kh, rg, bA);
    panel_ld(S, 1, kh, rg, bB);
    panel_ld(S, 2, kh, rg, bC);
    for (int p = 0; p < NPTOT; p += 4) PIPE4(accA)
}

// ---- dual-acc accumulate (m1s1 blocks): one 24-panel pipeline -------------
__device__ __forceinline__ void compute_accum16_8(
    const float* const* __restrict__ S, const float (* __restrict__ Ws)[8],
    int kh, int rg, u64 accA[4][4], u64 accB[4][4])
{
    constexpr int NPTOT = 24;
    #pragma unroll
    for (int r = 0; r < 4; r++)
        #pragma unroll
        for (int c = 0; c < 4; c++) { accA[r][c] = 0ull; accB[r][c] = 0ull; }

    float4 bA[4], bB[4], bC[4], bD[4];
    panel_ld(S, 0, kh, rg, bA);
    panel_ld(S, 1, kh, rg, bB);
    panel_ld(S, 2, kh, rg, bC);
    for (int p = 0;  p < 16;    p += 4) PIPE4(accA)
    for (int p = 16; p < NPTOT; p += 4) PIPE4(accB)
}

// ---- shfl-fold 16 k-slices -> 8, park partials in a Red bank --------------
__device__ __forceinline__ void reduce_to_red(
    u64 acc[4][4], float (* __restrict__ Red)[64][9], int tid)
{
    const int w = tid >> 5, rg = tid & 15;
    #pragma unroll
    for (int r = 0; r < 4; r++)
        #pragma unroll
        for (int c = 0; c < 4; c++)
            acc[r][c] = add2(acc[r][c], __shfl_xor_sync(0xffffffffu, acc[r][c], 16));
    if ((tid & 16) == 0) {
        #pragma unroll
        for (int r = 0; r < 4; r++)
            #pragma unroll
            for (int c = 0; c < 4; c++) {
                float2 v = upk2(acc[r][c]);
                // scalar stores (9-float rows would misalign float2)
                Red[w][rg*4 + r][2*c]   = v.x;
                Red[w][rg*4 + r][2*c+1] = v.y;
            }
    }
}

// ---- final: sum 8 partials, leaky update, tanh -> OutT smem tile ----------
// d_out rate values stay register-deferred (rr0/rr1, flushed next step).
__device__ __forceinline__ void finish_region(
    const float (* __restrict__ Red)[64][9], float biasv,
    bool add_stim, Smem& sm, float (* __restrict__ OutT)[72],
    float& x0, float& x1, float& rr0, float& rr1)
{
    const int tid = threadIdx.x;
    const int j = tid & 7;
    #pragma unroll
    for (int h = 0; h < 2; h++) {
        int b = (tid >> 3) + h*32;
        float s = 0.f;
        #pragma unroll
        for (int q = 0; q < 8; q++) s += Red[q][b][j];
        float v = s + biasv;
        if (add_stim) {
            #pragma unroll
            for (int k = 0; k < D_IN; k++)
                v = fmaf(sm.stim_s[b][k], sm.Win[k][j], v);
        }
        float& x = h ? x1 : x0;
        x = 0.8f*x + 0.2f*v;
        float rr = tanhf(x);
        (h ? rr1 : rr0) = rr;
        OutT[j][b] = rr;              // smem transpose tile (~2-way conflicts)
    }
}

// ---- coalesced g_rA flush: OutT[8][72] -> one 8x64 k-major region ---------
// All 256 threads: thread (jjl=tid>>5, b2=tid&31) moves one float2; per warp
// the stores cover one contiguous 256B g_rA row (fully coalesced).
__device__ __forceinline__ void flush_rates(
    const float (* __restrict__ OutT)[72], int pw, int reg, int jb, int tid)
{
    int jjl = tid >> 5, b2 = tid & 31;
    float2 v = *(const float2*)&OutT[jjl][b2*2];
    __stcg((float2*)&g_rA[pw][reg][jb + jjl][b2*2], v);
}

// ---------------------------------------------------------------------------
// Persistent RNN: weights in smem, X state in registers, release-atomic grid
// barrier; g_rA writes smem-transposed+coalesced; d_out deferred stores and
// stim staging issued AFTER the panel pipeline (off the critical load path).
// blocks [0,64): pmd (24 panels). [64,128): m1+s1 fused 24-panel pipeline.
// ---------------------------------------------------------------------------
__global__ void __launch_bounds__(256,1) rnn_persistent(
    const float* __restrict__ W_rec_m1, const float* __restrict__ W_rec_pmd,
    const float* __restrict__ W_rec_s1, const float* __restrict__ W_pmd_m1,
    const float* __restrict__ b_pmd_m1, const float* __restrict__ W_m1_pmd,
    const float* __restrict__ b_m1_pmd, const float* __restrict__ W_s1_pmd,
    const float* __restrict__ b_s1_pmd, const float* __restrict__ W_in_s1,
    const float* __restrict__ b_in_s1, const float* __restrict__ W_out,
    const float* __restrict__ b_out,   const float* __restrict__ W_fb,
    const float* __restrict__ b_fb,    const float* __restrict__ stim,
    float* __restrict__ d_out)
{
    extern __shared__ char sraw[];
    Smem& sm = *reinterpret_cast<Smem*>(sraw);

    const int tid = threadIdx.x, bid = blockIdx.x;
    const bool pmdB = bid < 64;
    const int jb = (pmdB ? bid : bid - 64) << 3;
    const int jj = jb + (tid & 7);
    const int b0 = tid >> 3;               // batch row for h=0 (h=1: +32)

    // ---- load weights into smem (once) ----
    if (pmdB) {
        for (int r = tid; r < NH; r += 256) {
            float wo0 = W_out[r*2], wo1 = W_out[r*2+1];
            #pragma unroll
            for (int q = 0; q < 8; q++) {
                int col = jb + q;
                sm.Ws[r][q]        = W_rec_pmd[r*NH + col];
                sm.Ws[NH + r][q]   = W_m1_pmd[r*NH + col]
                                   + wo0*W_fb[col] + wo1*W_fb[NH + col];
                sm.Ws[2*NH + r][q] = W_s1_pmd[r*NH + col];
            }
        }
    } else {
        for (int r = tid; r < NH; r += 256) {
            #pragma unroll
            for (int q = 0; q < 8; q++) {
                int col = jb + q;
                sm.Ws[r][q]        = W_rec_m1[r*NH + col];
                sm.Ws[NH + r][q]   = W_pmd_m1[r*NH + col];
                sm.Ws[2*NH + r][q] = W_rec_s1[r*NH + col];
            }
        }
        for (int i = tid; i < D_IN*8; i += 256)
            sm.Win[i>>3][i&7] = W_in_s1[(i>>3)*NH + jb + (i&7)];
    }

    // ---- fold biases into registers ----
    float bias0, bias_ex = 0.f, bias_s1 = 0.f;
    if (pmdB) {
        bias0   = b_m1_pmd[jj] + b_s1_pmd[jj] + b_fb[jj];
        bias_ex = b_out[0]*W_fb[jj] + b_out[1]*W_fb[NH + jj];
    } else {
        bias0   = b_pmd_m1[jj];
        bias_s1 = b_in_s1[jj];
    }

    // ---- zero parity-0 rates and t=0 rate slices ----
    {
        float* rA0 = &g_rA[0][0][0][0];
        for (int i = bid*256 + tid; i < 3*NH*BATCH; i += NBLK*256)
            __stcg(&rA0[i], 0.f);
        float* r0 = d_out + OUTS_SZ;
        for (int i = bid*256 + tid; i < BN; i += NBLK*256) {
            r0[i] = 0.f; r0[RSZ + i] = 0.f; r0[2*RSZ + i] = 0.f;
        }
    }

    float x_a0 = 0.f, x_a1 = 0.f;   // pmd (pmd-block) / m1 (m1s1-block)
    float x_b0 = 0.f, x_b1 = 0.f;   // s1 (m1s1-block)
    float r_a0 = 0.f, r_a1 = 0.f;   // deferred d_out rate values
    float r_b0 = 0.f, r_b1 = 0.f;

    unsigned mygen = ld_acq(&g_gen);
    grid_bar(&mygen);

    const int kh = tid >> 4, rg = tid & 15;
    u64 accA[4][4], accB[4][4];
    const float* S[3];

    for (int t = 1; t < T_STEPS; t++) {
        const int pr = (t-1) & 1, pw = t & 1;
        const float* Am1  = &g_rA[pr][0][0][0];
        const float* Apmd = &g_rA[pr][1][0][0];
        const float* As1  = &g_rA[pr][2][0][0];

        if (pmdB) {
            S[0] = Apmd; S[1] = Am1; S[2] = As1;
            compute_accum24(S, sm.Ws, kh, rg, accA);
            // deferred d_out flush — off the load path, hidden by the sync
            if (t > 1) {
                float* rp = d_out + OUTS_SZ + (size_t)(t-1)*BN + b0*NH + jj;
                rp[RSZ] = r_a0; rp[RSZ + 32*NH] = r_a1;
            }
            reduce_to_red(accA, sm.RedA, tid);
            __syncthreads();
            float bv = (t == 1) ? bias0 : (bias0 + bias_ex);
            finish_region(sm.RedA, bv, false, sm, sm.OutT[0],
                          x_a0, x_a1, r_a0, r_a1);
            __syncthreads();
            flush_rates(sm.OutT[0], pw, 1, jb, tid);
        } else {
            S[0] = Am1; S[1] = Apmd; S[2] = As1;
            compute_accum16_8(S, sm.Ws, kh, rg, accA, accB);
            // stim staging + deferred d_out flush — off the load path
            if (tid < 160)
                ((float4*)&sm.stim_s[0][0])[tid] =
                    __ldg((const float4*)(stim + (size_t)t*BATCH*D_IN) + tid);
            if (t > 1) {
                float* rp = d_out + OUTS_SZ + (size_t)(t-1)*BN + b0*NH + jj;
                rp[0] = r_a0;       rp[32*NH] = r_a1;
                rp[2*RSZ] = r_b0;   rp[2*RSZ + 32*NH] = r_b1;
            }
            reduce_to_red(accA, sm.RedA, tid);
            reduce_to_red(accB, sm.RedB, tid);
            __syncthreads();
            finish_region(sm.RedA, bias0,  false, sm, sm.OutT[0],
                          x_a0, x_a1, r_a0, r_a1);
            finish_region(sm.RedB, bias_s1, true, sm, sm.OutT[1],
                          x_b0, x_b1, r_b0, r_b1);
            __syncthreads();
            // merged flush: both regions in one pass (2 coalesced float2/thread)
            flush_rates(sm.OutT[0], pw, 0, jb, tid);
            flush_rates(sm.OutT[1], pw, 2, jb, tid);
        }
        grid_bar(&mygen);   // release-arrival; syncthreads protects Red/OutT
    }

    // ---- flush final step's deferred stores, then make them visible -------
    {
        float* rp = d_out + OUTS_SZ + (size_t)(T_STEPS-1)*BN + b0*NH + jj;
        if (pmdB) {
            rp[RSZ] = r_a0; rp[RSZ + 32*NH] = r_a1;
        } else {
            rp[0] = r_a0;       rp[32*NH] = r_a1;
            rp[2*RSZ] = r_b0;   rp[2*RSZ + 32*NH] = r_b1;
        }
    }
    grid_bar(&mygen);

    // ---- fused readout: outs[t] = r_m1[t] @ W_out + b_out (t>=1) ----------
    for (int o = bid*256 + tid; o < OUTS_SZ; o += NBLK*256) {
        int t = o >> 7;                  // 128 outputs per timestep
        int rr = o & 127;
        int b = rr >> 1, d = rr & 1;
        if (t == 0) { d_out[o] = 0.f; continue; }
        const float* rm = d_out + OUTS_SZ + (size_t)t*BN + b*NH;
        float a0=0.f, a1=0.f, a2=0.f, a3=0.f;
        for (int k = 0; k < NH; k += 4) {
            float4 r4 = __ldcg((const float4*)&rm[k]);
            a0 = fmaf(r4.x, W_out[(k+0)*2 + d], a0);
            a1 = fmaf(r4.y, W_out[(k+1)*2 + d], a1);
            a2 = fmaf(r4.z, W_out[(k+2)*2 + d], a2);
            a3 = fmaf(r4.w, W_out[(k+3)*2 + d], a3);
        }
        d_out[o] = b_out[d] + (a0 + a1) + (a2 + a3);
    }
}

// ---------------------------------------------------------------------------
extern "C" void kernel_launch(void* const* d_in, const int* in_sizes, int n_in,
                              void* d_out, int out_size)
{
    const float* stim      = (const float*)d_in[0];
    const float* W_rec_m1  = (const float*)d_in[1];
    const float* W_rec_pmd = (const float*)d_in[2];
    const float* W_rec_s1  = (const float*)d_in[3];
    const float* W_pmd_m1  = (const float*)d_in[4];
    const float* b_pmd_m1  = (const float*)d_in[5];
    const float* W_m1_pmd  = (const float*)d_in[6];
    const float* b_m1_pmd  = (const float*)d_in[7];
    const float* W_s1_pmd  = (const float*)d_in[8];
    const float* b_s1_pmd  = (const float*)d_in[9];
    const float* W_in_s1   = (const float*)d_in[10];
    const float* b_in_s1   = (const float*)d_in[11];
    const float* W_out_m1  = (const float*)d_in[12];
    const float* b_out_m1  = (const float*)d_in[13];
    const float* W_fb_pmd  = (const float*)d_in[14];
    const float* b_fb_pmd  = (const float*)d_in[15];
    float* out = (float*)d_out;

    // Idempotent, capture-safe; no static guard.
    cudaFuncSetAttribute(rnn_persistent,
                         cudaFuncAttributeMaxDynamicSharedMemorySize,
                         (int)sizeof(Smem));

    rnn_persistent<<<NBLK, 256, sizeof(Smem)>>>(
        W_rec_m1, W_rec_pmd, W_rec_s1, W_pmd_m1, b_pmd_m1, W_m1_pmd,
        b_m1_pmd, W_s1_pmd, b_s1_pmd, W_in_s1, b_in_s1,
        W_out_m1, b_out_m1, W_fb_pmd, b_fb_pmd, stim, out);
}